// round 12
// baseline (speedup 1.0000x reference)
#include <cuda_runtime.h>
#include <cuda_fp16.h>
#include <cstdint>
#include <math.h>

// Problem constants
#define N_IMG 4
#define C_IN  256
#define HW    16384        // 128*128
#define MLP   128
#define NA    16
#define NB    64
#define ALPHA 300.0f

// ---------------------------------------------------------------------------
// MLP kernel SMEM layout (bytes)
//   w1 [o=128][k=256] fp16, pitch 528                 -> 67584
//   w2 [a=16][o=128]  fp16, pitch 272                 -> 4352
//   x  4-stage ring [k=16][p=128] fp32, pitch 528     -> 33792
//   b1 512, b2 64
// ---------------------------------------------------------------------------
#define W1_OFF   0
#define W2_OFF   67584
#define XS_OFF   71936
#define B1S_OFF  105728
#define B2S_OFF  106240
#define SMEM_TOTAL 106304

#define W1_PITCH 528
#define W2_PITCH 272
#define XS_PITCH 528                  // 132 floats per k-row
#define XSTAGE_SZ (16 * XS_PITCH)     // 8448 per stage

__device__ __forceinline__ uint32_t smem_u32(const void* p) {
    uint32_t a;
    asm("{ .reg .u64 t; cvta.to.shared.u64 t, %1; cvt.u32.u64 %0, t; }" : "=r"(a) : "l"(p));
    return a;
}
__device__ __forceinline__ void ldsm_x4(uint32_t& r0, uint32_t& r1, uint32_t& r2, uint32_t& r3,
                                        uint32_t addr) {
    asm volatile("ldmatrix.sync.aligned.m8n8.x4.shared.b16 {%0,%1,%2,%3}, [%4];"
                 : "=r"(r0), "=r"(r1), "=r"(r2), "=r"(r3) : "r"(addr));
}
__device__ __forceinline__ void mma16816(float* c, const uint32_t* a, const uint32_t* b) {
    asm volatile(
        "mma.sync.aligned.m16n8k16.row.col.f32.f16.f16.f32 "
        "{%0,%1,%2,%3}, {%4,%5,%6,%7}, {%8,%9}, {%0,%1,%2,%3};"
        : "+f"(c[0]), "+f"(c[1]), "+f"(c[2]), "+f"(c[3])
        : "r"(a[0]), "r"(a[1]), "r"(a[2]), "r"(a[3]), "r"(b[0]), "r"(b[1]));
}
__device__ __forceinline__ uint32_t h2exp2_u(uint32_t arg) {
    uint32_t r;
    asm("ex2.approx.f16x2 %0, %1;" : "=r"(r) : "r"(arg));
    return r;
}
__device__ __forceinline__ uint32_t packh2(float a, float b) {
    __half2 h = __floats2half2_rn(a, b);
    return *(uint32_t*)&h;
}
__device__ __forceinline__ void cp16(uint32_t dst, const void* src) {
    asm volatile("cp.async.cg.shared.global [%0], [%1], 16;"
                 :: "r"(dst), "l"(src) : "memory");
}

// Scratch (allocation-free rule: __device__ globals)
__device__ uint4 g_w1v[4096];                 // w1 fp16 [o=128][k=256], 8 halves/uint4
__device__ uint4 g_w2v[256];                  // w2 fp16 [a=16][o=128]
__device__ float g_A[N_IMG * HW * NA];        // attractors, pixel-major [px][16]

__global__ void prep_kernel(const float* __restrict__ w1, const float* __restrict__ w2) {
    int i = blockIdx.x * 256 + threadIdx.x;
    const float* src;
    uint4* dst;
    if (i < 4096)      { src = w1 + 8 * i;          dst = &g_w1v[i]; }
    else if (i < 4352) { src = w2 + 8 * (i - 4096); dst = &g_w2v[i - 4096]; }
    else return;
    uint4 v;
    v.x = packh2(src[0], src[1]);
    v.y = packh2(src[2], src[3]);
    v.z = packh2(src[4], src[5]);
    v.w = packh2(src[6], src[7]);
    *dst = v;
}

extern __shared__ char smem[];

// ---------------------------------------------------------------------------
// MLP kernel: 128 pixels/block, 256 thr (8 warps; each warp 16 pixels).
// All staging (weights + x ring) via cp.async.cg. GEMM1 -> relu/pack (regs)
// -> GEMM2 -> softplus -> store A pixel-major.
// ---------------------------------------------------------------------------
__global__ __launch_bounds__(256, 2) void mlp_kernel(
    const float* __restrict__ x,
    const float* __restrict__ b1,
    const float* __restrict__ b2)
{
    const int tid = threadIdx.x;
    const int L   = tid & 31;
    const int wid = tid >> 5;
    const int pix_base = blockIdx.x * 128;
    const int img = pix_base >> 14;
    const int hw0 = pix_base & (HW - 1);
    const uint32_t sb = smem_u32(smem);

    const float* xgb = x + (size_t)img * C_IN * HW + hw0;

    // ---- weights + biases via cp.async (group 0) ----
#pragma unroll
    for (int i = 0; i < 16; i++) {
        int idx = tid + i * 256;             // 0..4095
        int o = idx >> 5, kq = idx & 31;
        cp16(sb + W1_OFF + (uint32_t)(o * W1_PITCH + kq * 16), g_w1v + idx);
    }
    {
        int a = tid >> 4, kq = tid & 15;
        cp16(sb + W2_OFF + (uint32_t)(a * W2_PITCH + kq * 16), g_w2v + tid);
        if (tid < 32) cp16(sb + B1S_OFF + tid * 16, b1 + tid * 4);
        if (tid < 4)  cp16(sb + B2S_OFF + tid * 16, b2 + tid * 4);
    }
    asm volatile("cp.async.commit_group;" ::: "memory");

    // ---- x stage issue: 16 k-rows x 128 px fp32, 2 x 16B per thread ----
    const int c0r = tid >> 5,          c0q = tid & 31;
    const int c1r = (tid + 256) >> 5,  c1q = tid & 31;
    auto issue_stage = [&](int s) {
        uint32_t dst = sb + XS_OFF + (uint32_t)((s & 3) * XSTAGE_SZ);
        const float* s0 = xgb + (size_t)(s * 16 + c0r) * HW + c0q * 4;
        const float* s1 = xgb + (size_t)(s * 16 + c1r) * HW + c1q * 4;
        cp16(dst + (uint32_t)(c0r * XS_PITCH + c0q * 16), s0);
        cp16(dst + (uint32_t)(c1r * XS_PITCH + c1q * 16), s1);
        asm volatile("cp.async.commit_group;" ::: "memory");
    };

    issue_stage(0);
    issue_stage(1);
    issue_stage(2);

    asm volatile("cp.async.wait_group 2;" ::: "memory");   // weights + stage 0 done
    __syncthreads();

    // ---- GEMM1: C[p16][o128] in regs, 16 k-steps, prefetch depth 3 ----
    const int p0 = wid * 16;
    float acc[16][4];
#pragma unroll
    for (int nt = 0; nt < 16; nt++)
#pragma unroll
        for (int j = 0; j < 4; j++) acc[nt][j] = 0.0f;

    const int g  = L >> 2;
    const int t2 = (L & 3) * 2;
    const uint32_t w_row  = (uint32_t)((L & 7) + ((L >> 4) << 3));
    const uint32_t w_colo = (uint32_t)(((L >> 3) & 1) << 3);
    const uint32_t w1ls_base = sb + W1_OFF + w_row * W1_PITCH + w_colo * 2;
    const uint32_t w2ls_base = sb + W2_OFF + w_row * W2_PITCH + w_colo * 2;

#pragma unroll
    for (int s = 0; s < 16; s++) {
        if (s + 3 < 16) issue_stage(s + 3);

        const float* xb = (const float*)(smem + XS_OFF + (s & 3) * XSTAGE_SZ);
        const float* pc  = xb + p0 + g;
        const float* pc8 = pc + 8;
        uint32_t af[4];
        af[0] = packh2(pc [ t2      * 132], pc [(t2 + 1) * 132]);
        af[1] = packh2(pc8[ t2      * 132], pc8[(t2 + 1) * 132]);
        af[2] = packh2(pc [(t2 + 8) * 132], pc [(t2 + 9) * 132]);
        af[3] = packh2(pc8[(t2 + 8) * 132], pc8[(t2 + 9) * 132]);

#pragma unroll
        for (int nt2 = 0; nt2 < 8; nt2++) {
            uint32_t bw[4];
            ldsm_x4(bw[0], bw[1], bw[2], bw[3],
                    w1ls_base + (uint32_t)(nt2 * 16) * W1_PITCH + (uint32_t)(s * 16) * 2);
            mma16816(acc[2 * nt2],     af, bw);
            mma16816(acc[2 * nt2 + 1], af, bw + 2);
        }

        if (s < 15) {
            if (s <= 12)      { asm volatile("cp.async.wait_group 2;" ::: "memory"); }
            else if (s == 13) { asm volatile("cp.async.wait_group 1;" ::: "memory"); }
            else              { asm volatile("cp.async.wait_group 0;" ::: "memory"); }
            __syncthreads();
        }
    }

    // ---- epilogue1: +b1, relu, pack fp16 -> A2 frags in regs ----
    uint32_t h2r[32];
    {
        const float2* b1f2 = (const float2*)(smem + B1S_OFF);
#pragma unroll
        for (int nt = 0; nt < 16; nt++) {
            float2 bb = b1f2[nt * 4 + (L & 3)];
            float v0 = fmaxf(acc[nt][0] + bb.x, 0.0f);
            float v1 = fmaxf(acc[nt][1] + bb.y, 0.0f);
            float v2 = fmaxf(acc[nt][2] + bb.x, 0.0f);
            float v3 = fmaxf(acc[nt][3] + bb.y, 0.0f);
            h2r[2 * nt]     = packh2(v0, v1);
            h2r[2 * nt + 1] = packh2(v2, v3);
        }
    }

    // ---- GEMM2: z[p16][a16], K = 128 (8 ksteps), A = h2r in regs ----
    float zacc[2][4];
#pragma unroll
    for (int nt = 0; nt < 2; nt++)
#pragma unroll
        for (int j = 0; j < 4; j++) zacc[nt][j] = 0.0f;

#pragma unroll
    for (int s2 = 0; s2 < 8; s2++) {
        uint32_t bw[4];
        ldsm_x4(bw[0], bw[1], bw[2], bw[3], w2ls_base + (uint32_t)(s2 * 16) * 2);
        mma16816(zacc[0], &h2r[4 * s2], bw);
        mma16816(zacc[1], &h2r[4 * s2], bw + 2);
    }

    // ---- +b2, softplus, store A pixel-major [gpix][16] ----
    {
        const float2* b2f2 = (const float2*)(smem + B2S_OFF);
        const int prow = L >> 2;
        const int acol = 2 * (L & 3);
        const int gpix0 = pix_base + p0 + prow;       // img*HW + hw already
#pragma unroll
        for (int nt = 0; nt < 2; nt++) {
            float2 bb = b2f2[nt * 4 + (L & 3)];
            float z0 = zacc[nt][0] + bb.x;
            float z1 = zacc[nt][1] + bb.y;
            float z2 = zacc[nt][2] + bb.x;
            float z3 = zacc[nt][3] + bb.y;
            float s0  = fmaxf(z0, 0.0f) + __logf(1.0f + __expf(-fabsf(z0)));
            float s1  = fmaxf(z1, 0.0f) + __logf(1.0f + __expf(-fabsf(z1)));
            float s2v = fmaxf(z2, 0.0f) + __logf(1.0f + __expf(-fabsf(z2)));
            float s3  = fmaxf(z3, 0.0f) + __logf(1.0f + __expf(-fabsf(z3)));
            *(float2*)(g_A + (size_t)gpix0 * NA + nt * 8 + acol)       = make_float2(s0, s1);
            *(float2*)(g_A + (size_t)(gpix0 + 8) * NA + nt * 8 + acol) = make_float2(s2v, s3);
        }
    }
}

// ---------------------------------------------------------------------------
// Attract kernel: 128 px/block x 2 halves, no smem, high occupancy.
// A from g_A (2x LDG.128), dual half2 accumulators, f16x2 exp.
// ---------------------------------------------------------------------------
__global__ __launch_bounds__(256) void attract_kernel(
    const float* __restrict__ b_prev,
    float* __restrict__ out,
    int copies)
{
    const int tid = threadIdx.x;
    const int px_l = tid & 127;
    const int half = tid >> 7;
    const int gpix = blockIdx.x * 128 + px_l;
    const int img = gpix >> 14;
    const int hw  = gpix & (HW - 1);

    // load A[gpix][16], pack to half2
    uint32_t AvH2[8];
    {
        const float4* ap = (const float4*)(g_A + (size_t)gpix * NA);
        float4 v0 = ap[0], v1 = ap[1], v2 = ap[2], v3 = ap[3];
        AvH2[0] = packh2(v0.x, v0.y); AvH2[1] = packh2(v0.z, v0.w);
        AvH2[2] = packh2(v1.x, v1.y); AvH2[3] = packh2(v1.z, v1.w);
        AvH2[4] = packh2(v2.x, v2.y); AvH2[5] = packh2(v2.z, v2.w);
        AvH2[6] = packh2(v3.x, v3.y); AvH2[7] = packh2(v3.z, v3.w);
    }

    const float* bp = b_prev + ((size_t)img * NB + half * 32) * HW + hw;
    float* o0 = out + ((size_t)img * NB + half * 32) * HW + hw;
    float* o1 = o0 + (size_t)N_IMG * NB * HW;
    const __half2 KH2 = __float2half2_rn(-432.80852f);   // -ALPHA * log2(e)

    for (int c = 0; c < 4; c++) {            // 4 chunks x 8 bins
        float bcv[8], rv[8];
#pragma unroll
        for (int j = 0; j < 8; j++)
            bcv[j] = bp[(size_t)(c * 8 + j) * HW];
#pragma unroll
        for (int j = 0; j < 8; j++) {
            float bc = bcv[j];
            __half2 bch = __float2half2_rn(bc);
            // dual accumulators (halves accumulation error vs single chain)
            __half2 dh0 = __hsub2(*(const __half2*)&AvH2[0], bch);
            __half2 ar0 = __hmul2(__hmul2(dh0, dh0), KH2);
            uint32_t e0 = h2exp2_u(*(uint32_t*)&ar0);
            __half2 accA = __hmul2(*(__half2*)&e0, dh0);
            __half2 dh1 = __hsub2(*(const __half2*)&AvH2[1], bch);
            __half2 ar1 = __hmul2(__hmul2(dh1, dh1), KH2);
            uint32_t e1 = h2exp2_u(*(uint32_t*)&ar1);
            __half2 accB = __hmul2(*(__half2*)&e1, dh1);
#pragma unroll
            for (int i = 2; i < 8; i += 2) {
                __half2 dha = __hsub2(*(const __half2*)&AvH2[i], bch);
                __half2 ara = __hmul2(__hmul2(dha, dha), KH2);
                uint32_t ea = h2exp2_u(*(uint32_t*)&ara);
                accA = __hfma2(*(__half2*)&ea, dha, accA);
                __half2 dhb = __hsub2(*(const __half2*)&AvH2[i + 1], bch);
                __half2 arb = __hmul2(__hmul2(dhb, dhb), KH2);
                uint32_t eb = h2exp2_u(*(uint32_t*)&arb);
                accB = __hfma2(*(__half2*)&eb, dhb, accB);
            }
            float2 fa = __half22float2(accA);
            float2 fb = __half22float2(accB);
            rv[j] = bc + ((fa.x + fa.y) + (fb.x + fb.y));
        }
#pragma unroll
        for (int j = 0; j < 8; j++) {
            o0[(size_t)(c * 8 + j) * HW] = rv[j];
            if (copies >= 2) o1[(size_t)(c * 8 + j) * HW] = rv[j];
        }
    }
}

// ---------------------------------------------------------------------------
// Launch. Inputs (metadata order): x, b_prev, w1, b1, w2, b2.
// ---------------------------------------------------------------------------
extern "C" void kernel_launch(void* const* d_in, const int* in_sizes, int n_in,
                              void* d_out, int out_size) {
    const float* x      = (const float*)d_in[0];
    const float* b_prev = (const float*)d_in[1];
    const float* w1     = (const float*)d_in[2];
    const float* b1     = (const float*)d_in[3];
    const float* w2     = (const float*)d_in[4];
    const float* b2     = (const float*)d_in[5];
    float* out = (float*)d_out;

    const int one_out = N_IMG * NB * HW;
    int copies = out_size / one_out;

    static bool attr_set = false;
    if (!attr_set) {
        cudaFuncSetAttribute(mlp_kernel,
                             cudaFuncAttributeMaxDynamicSharedMemorySize, SMEM_TOTAL);
        attr_set = true;
    }

    prep_kernel<<<17, 256>>>(w1, w2);
    mlp_kernel<<<(N_IMG * HW) / 128, 256, SMEM_TOTAL>>>(x, b1, b2);
    attract_kernel<<<(N_IMG * HW) / 128, 256>>>(b_prev, out, copies);
}

// round 14
// speedup vs baseline: 1.1558x; 1.1558x over previous
#include <cuda_runtime.h>
#include <cuda_fp16.h>
#include <cstdint>
#include <math.h>

// Problem constants
#define N_IMG 4
#define C_IN  256
#define HW    16384        // 128*128
#define MLP   128
#define NA    16
#define NB    64
#define ALPHA 300.0f

// ---------------------------------------------------------------------------
// SMEM layout (bytes)
//   w1 [o=128][k=256] fp16, pitch 528                 -> 67584
//   w2 [a=16][o=128]  fp16, pitch 272                 -> 4352
//   x  4-stage ring [k=16][p=128] fp32, pitch 528     -> 33792
//   z  per-warp [p=16][a=16] f32, pitch 72            -> 9216
//   b1 512, b2 64
// ---------------------------------------------------------------------------
#define W1_OFF   0
#define W2_OFF   67584
#define XS_OFF   71936
#define Z_OFF    105728
#define B1S_OFF  114944
#define B2S_OFF  115456
#define SMEM_TOTAL 115520

#define W1_PITCH 528
#define W2_PITCH 272
#define XS_PITCH 528                  // 132 floats per k-row
#define XSTAGE_SZ (16 * XS_PITCH)     // 8448 per stage
#define Z_PITCH  72

__device__ __forceinline__ uint32_t smem_u32(const void* p) {
    uint32_t a;
    asm("{ .reg .u64 t; cvta.to.shared.u64 t, %1; cvt.u32.u64 %0, t; }" : "=r"(a) : "l"(p));
    return a;
}
__device__ __forceinline__ void ldsm_x4(uint32_t& r0, uint32_t& r1, uint32_t& r2, uint32_t& r3,
                                        uint32_t addr) {
    asm volatile("ldmatrix.sync.aligned.m8n8.x4.shared.b16 {%0,%1,%2,%3}, [%4];"
                 : "=r"(r0), "=r"(r1), "=r"(r2), "=r"(r3) : "r"(addr));
}
__device__ __forceinline__ void mma16816(float* c, const uint32_t* a, const uint32_t* b) {
    asm volatile(
        "mma.sync.aligned.m16n8k16.row.col.f32.f16.f16.f32 "
        "{%0,%1,%2,%3}, {%4,%5,%6,%7}, {%8,%9}, {%0,%1,%2,%3};"
        : "+f"(c[0]), "+f"(c[1]), "+f"(c[2]), "+f"(c[3])
        : "r"(a[0]), "r"(a[1]), "r"(a[2]), "r"(a[3]), "r"(b[0]), "r"(b[1]));
}
__device__ __forceinline__ uint32_t h2exp2_u(uint32_t arg) {
    uint32_t r;
    asm("ex2.approx.f16x2 %0, %1;" : "=r"(r) : "r"(arg));
    return r;
}
__device__ __forceinline__ uint32_t packh2(float a, float b) {
    __half2 h = __floats2half2_rn(a, b);
    return *(uint32_t*)&h;
}

// fp16 weights prepacked once (allocation-free: __device__ globals)
__device__ uint4 g_w1v[4096];    // w1 [o=128][k=256] halves, 8 per uint4
__device__ uint4 g_w2v[256];     // w2 [a=16][o=128]

// Fast prep: 68 blocks x 256 thr, one float2 -> half2 per thread (coalesced).
__global__ void prep_kernel(const float* __restrict__ w1, const float* __restrict__ w2) {
    int i = blockIdx.x * 256 + threadIdx.x;     // 0..17407
    uint32_t* w1h = (uint32_t*)g_w1v;           // 16384 half2
    uint32_t* w2h = (uint32_t*)g_w2v;           // 1024 half2
    if (i < 16384) {
        float2 v = *(const float2*)(w1 + 2 * i);
        w1h[i] = packh2(v.x, v.y);
    } else {
        int j = i - 16384;                      // 0..1023
        float2 v = *(const float2*)(w2 + 2 * j);
        w2h[j] = packh2(v.x, v.y);
    }
}

extern __shared__ char smem[];

// ---------------------------------------------------------------------------
// Fused: 128 pixels/block, 256 thr (8 warps; each warp owns 16 pixels).
// x: cp.async.cg 4-stage ring, prefetch depth 3. GEMM1 -> relu/pack (regs)
// -> GEMM2 -> softplus -> warp-local z -> all-half2 attractor (double-
// buffered bc loads) -> out.
// ---------------------------------------------------------------------------
__global__ __launch_bounds__(256, 2) void fused_kernel(
    const float* __restrict__ x,
    const float* __restrict__ b1,
    const float* __restrict__ b2,
    const float* __restrict__ b_prev,
    float* __restrict__ out,
    int copies)
{
    const int tid = threadIdx.x;
    const int L   = tid & 31;
    const int wid = tid >> 5;
    const int pix_base = blockIdx.x * 128;
    const int img = pix_base >> 14;
    const int hw0 = pix_base & (HW - 1);
    const uint32_t sb = smem_u32(smem);

    const float* xgb = x + (size_t)img * C_IN * HW + hw0;   // block x slice

    // ---- cp.async stage issue: 16 k-rows x 128 px fp32, 2 x 16B per thread ----
    const int c0r = tid >> 5,          c0q = tid & 31;          // chunk tid
    const int c1r = (tid + 256) >> 5,  c1q = tid & 31;          // chunk tid+256
    auto issue_stage = [&](int s) {
        uint32_t dst = sb + XS_OFF + (uint32_t)((s & 3) * XSTAGE_SZ);
        const float* s0 = xgb + (size_t)(s * 16 + c0r) * HW + c0q * 4;
        const float* s1 = xgb + (size_t)(s * 16 + c1r) * HW + c1q * 4;
        asm volatile("cp.async.cg.shared.global [%0], [%1], 16;"
                     :: "r"(dst + (uint32_t)(c0r * XS_PITCH + c0q * 16)), "l"(s0) : "memory");
        asm volatile("cp.async.cg.shared.global [%0], [%1], 16;"
                     :: "r"(dst + (uint32_t)(c1r * XS_PITCH + c1q * 16)), "l"(s1) : "memory");
        asm volatile("cp.async.commit_group;" ::: "memory");
    };

    issue_stage(0);
    issue_stage(1);
    issue_stage(2);

    // ---- stage weights + biases (overlaps with cp.async stages 0-2) ----
#pragma unroll
    for (int i = 0; i < 16; i++) {
        int idx = tid + i * 256;             // 0..4095
        int o = idx >> 5, kq = idx & 31;
        *(uint4*)(smem + W1_OFF + o * W1_PITCH + kq * 16) = g_w1v[idx];
    }
    {
        int a = tid >> 4, kq = tid & 15;
        *(uint4*)(smem + W2_OFF + a * W2_PITCH + kq * 16) = g_w2v[tid];
        if (tid < 128) ((float*)(smem + B1S_OFF))[tid] = b1[tid];
        if (tid < 16)  ((float*)(smem + B2S_OFF))[tid] = b2[tid];
    }

    asm volatile("cp.async.wait_group 2;" ::: "memory");   // stage 0 done
    __syncthreads();                                        // weights + stage 0 visible

    // ---- GEMM1: C[p16][o128] in regs, 16 k-steps, prefetch depth 3 ----
    const int p0 = wid * 16;
    float acc[16][4];
#pragma unroll
    for (int nt = 0; nt < 16; nt++)
#pragma unroll
        for (int j = 0; j < 4; j++) acc[nt][j] = 0.0f;

    const int g  = L >> 2;
    const int t2 = (L & 3) * 2;
    const uint32_t w_row  = (uint32_t)((L & 7) + ((L >> 4) << 3));
    const uint32_t w_colo = (uint32_t)(((L >> 3) & 1) << 3);
    const uint32_t w1ls_base = sb + W1_OFF + w_row * W1_PITCH + w_colo * 2;
    const uint32_t w2ls_base = sb + W2_OFF + w_row * W2_PITCH + w_colo * 2;

#pragma unroll
    for (int s = 0; s < 16; s++) {
        if (s + 3 < 16) issue_stage(s + 3);   // slot (s-1)&3, freed by last sync

        // A fragment from fp32 stage [k][p] (pitch 132 floats): conflict-free
        const float* xb = (const float*)(smem + XS_OFF + (s & 3) * XSTAGE_SZ);
        const float* pc  = xb + p0 + g;        // pixel column g
        const float* pc8 = pc + 8;             // pixel column g+8
        uint32_t af[4];
        af[0] = packh2(pc [ t2      * 132], pc [(t2 + 1) * 132]);
        af[1] = packh2(pc8[ t2      * 132], pc8[(t2 + 1) * 132]);
        af[2] = packh2(pc [(t2 + 8) * 132], pc [(t2 + 9) * 132]);
        af[3] = packh2(pc8[(t2 + 8) * 132], pc8[(t2 + 9) * 132]);

#pragma unroll
        for (int nt2 = 0; nt2 < 8; nt2++) {
            uint32_t bw[4];
            ldsm_x4(bw[0], bw[1], bw[2], bw[3],
                    w1ls_base + (uint32_t)(nt2 * 16) * W1_PITCH + (uint32_t)(s * 16) * 2);
            mma16816(acc[2 * nt2],     af, bw);
            mma16816(acc[2 * nt2 + 1], af, bw + 2);
        }

        if (s < 15) {
            // need stage s+1 complete before next iteration's reads
            if (s <= 12)      { asm volatile("cp.async.wait_group 2;" ::: "memory"); }
            else if (s == 13) { asm volatile("cp.async.wait_group 1;" ::: "memory"); }
            else              { asm volatile("cp.async.wait_group 0;" ::: "memory"); }
            __syncthreads();
        }
    }

    // ---- epilogue1: +b1, relu, pack fp16 -> A2 frags in regs ----
    uint32_t h2r[32];
    {
        const float2* b1f2 = (const float2*)(smem + B1S_OFF);
#pragma unroll
        for (int nt = 0; nt < 16; nt++) {
            float2 bb = b1f2[nt * 4 + (L & 3)];
            float v0 = fmaxf(acc[nt][0] + bb.x, 0.0f);
            float v1 = fmaxf(acc[nt][1] + bb.y, 0.0f);
            float v2 = fmaxf(acc[nt][2] + bb.x, 0.0f);
            float v3 = fmaxf(acc[nt][3] + bb.y, 0.0f);
            h2r[2 * nt]     = packh2(v0, v1);
            h2r[2 * nt + 1] = packh2(v2, v3);
        }
    }

    // ---- GEMM2: z[p16][a16], K = 128 (8 ksteps), A = h2r in regs ----
    float zacc[2][4];
#pragma unroll
    for (int nt = 0; nt < 2; nt++)
#pragma unroll
        for (int j = 0; j < 4; j++) zacc[nt][j] = 0.0f;

#pragma unroll
    for (int s2 = 0; s2 < 8; s2++) {
        uint32_t bw[4];
        ldsm_x4(bw[0], bw[1], bw[2], bw[3], w2ls_base + (uint32_t)(s2 * 16) * 2);
        mma16816(zacc[0], &h2r[4 * s2], bw);
        mma16816(zacc[1], &h2r[4 * s2], bw + 2);
    }

    // ---- +b2, softplus -> warp-local z smem [p16][a16] ----
    char* warpz = smem + Z_OFF + wid * (16 * Z_PITCH);
    {
        const float2* b2f2 = (const float2*)(smem + B2S_OFF);
        int lrow = L >> 2;
        int acol = 2 * (L & 3);
#pragma unroll
        for (int nt = 0; nt < 2; nt++) {
            float2 bb = b2f2[nt * 4 + (L & 3)];
            float z0 = zacc[nt][0] + bb.x;
            float z1 = zacc[nt][1] + bb.y;
            float z2 = zacc[nt][2] + bb.x;
            float z3 = zacc[nt][3] + bb.y;
            float s0  = fmaxf(z0, 0.0f) + log1pf(__expf(-fabsf(z0)));
            float s1  = fmaxf(z1, 0.0f) + log1pf(__expf(-fabsf(z1)));
            float s2v = fmaxf(z2, 0.0f) + log1pf(__expf(-fabsf(z2)));
            float s3  = fmaxf(z3, 0.0f) + log1pf(__expf(-fabsf(z3)));
            *(float2*)(warpz + (size_t)lrow * Z_PITCH + (nt * 8 + acol) * 4)
                = make_float2(s0, s1);
            *(float2*)(warpz + (size_t)(lrow + 8) * Z_PITCH + (nt * 8 + acol) * 4)
                = make_float2(s2v, s3);
        }
    }
    __syncwarp();

    // ---- attractor: 2 lanes per pixel (16 px), 32 bins each, all-half2,
    //      bc loads double-buffered across 8-bin chunks ----
    {
        const int px_l = L & 15;
        const int half = L >> 4;
        const float* zr = (const float*)(warpz + (size_t)px_l * Z_PITCH);
        uint32_t AvH2[8];
#pragma unroll
        for (int q = 0; q < 8; q++) {
            float2 v = *(const float2*)(zr + 2 * q);
            AvH2[q] = packh2(v.x, v.y);
        }

        const int gpix = hw0 + p0 + px_l;
        const float* bp = b_prev + (size_t)img * NB * HW + gpix + (size_t)(half * 32) * HW;
        float* o0 = out + (size_t)img * NB * HW + gpix + (size_t)(half * 32) * HW;
        float* o1 = o0 + (size_t)N_IMG * NB * HW;
        const __half2 KH2 = __float2half2_rn(-432.80852f);   // -ALPHA * log2(e)

        float bcv[2][8];
#pragma unroll
        for (int j = 0; j < 8; j++)
            bcv[0][j] = bp[(size_t)j * HW];

        for (int c = 0; c < 4; c++) {            // 4 chunks x 8 bins
            const int cur = c & 1, nxt = cur ^ 1;
            if (c < 3) {
#pragma unroll
                for (int j = 0; j < 8; j++)      // prefetch next chunk's bc
                    bcv[nxt][j] = bp[(size_t)((c + 1) * 8 + j) * HW];
            }
            float rv[8];
#pragma unroll
            for (int j = 0; j < 8; j++) {
                float bc = bcv[cur][j];
                __half2 bch = __float2half2_rn(bc);
                // dual accumulators for MUFU/FMA ILP
                __half2 dh0 = __hsub2(*(const __half2*)&AvH2[0], bch);
                __half2 ar0 = __hmul2(__hmul2(dh0, dh0), KH2);
                uint32_t e0 = h2exp2_u(*(uint32_t*)&ar0);
                __half2 accA = __hmul2(*(__half2*)&e0, dh0);
                __half2 dh1 = __hsub2(*(const __half2*)&AvH2[1], bch);
                __half2 ar1 = __hmul2(__hmul2(dh1, dh1), KH2);
                uint32_t e1 = h2exp2_u(*(uint32_t*)&ar1);
                __half2 accB = __hmul2(*(__half2*)&e1, dh1);
#pragma unroll
                for (int i = 2; i < 8; i += 2) {
                    __half2 dha = __hsub2(*(const __half2*)&AvH2[i], bch);
                    __half2 ara = __hmul2(__hmul2(dha, dha), KH2);
                    uint32_t ea = h2exp2_u(*(uint32_t*)&ara);
                    accA = __hfma2(*(__half2*)&ea, dha, accA);
                    __half2 dhb = __hsub2(*(const __half2*)&AvH2[i + 1], bch);
                    __half2 arb = __hmul2(__hmul2(dhb, dhb), KH2);
                    uint32_t eb = h2exp2_u(*(uint32_t*)&arb);
                    accB = __hfma2(*(__half2*)&eb, dhb, accB);
                }
                float2 fa = __half22float2(accA);
                float2 fb = __half22float2(accB);
                rv[j] = bc + ((fa.x + fa.y) + (fb.x + fb.y));
            }
#pragma unroll
            for (int j = 0; j < 8; j++) {
                o0[(size_t)(c * 8 + j) * HW] = rv[j];
                if (copies >= 2) o1[(size_t)(c * 8 + j) * HW] = rv[j];
            }
        }
    }
}

// ---------------------------------------------------------------------------
// Launch. Inputs (metadata order): x, b_prev, w1, b1, w2, b2.
// ---------------------------------------------------------------------------
extern "C" void kernel_launch(void* const* d_in, const int* in_sizes, int n_in,
                              void* d_out, int out_size) {
    const float* x      = (const float*)d_in[0];
    const float* b_prev = (const float*)d_in[1];
    const float* w1     = (const float*)d_in[2];
    const float* b1     = (const float*)d_in[3];
    const float* w2     = (const float*)d_in[4];
    const float* b2     = (const float*)d_in[5];
    float* out = (float*)d_out;

    const int one_out = N_IMG * NB * HW;
    int copies = out_size / one_out;

    static bool attr_set = false;
    if (!attr_set) {
        cudaFuncSetAttribute(fused_kernel,
                             cudaFuncAttributeMaxDynamicSharedMemorySize, SMEM_TOTAL);
        attr_set = true;
    }

    prep_kernel<<<68, 256>>>(w1, w2);
    fused_kernel<<<(N_IMG * HW) / 128, 256, SMEM_TOTAL>>>(
        x, b1, b2, b_prev, out, copies);
}